// round 4
// baseline (speedup 1.0000x reference)
#include <cuda_runtime.h>
#include <cuda_bf16.h>
#include <math.h>

#define NN 50000
#define EE 800000
#define GG 64
#define DD 128
#define BN_EPS 1e-5f

// ---------------- scratch (device globals; no allocation) ----------------
// __align__(16) REQUIRED: accessed through float4* casts.
__device__ __align__(16) float g_h[NN * DD];        // post-GEMM features (= bn(x) @ W exactly)
__device__ __align__(16) float g_act[NN * DD];      // post-aggregate/relu activations
__device__ __align__(16) int   g_csr_src[EE];
__device__ __align__(16) float g_csr_coef[EE];
__device__ __align__(16) int   g_rowptr[NN + 1];
__device__ __align__(16) int   g_counts[NN];
__device__ __align__(16) int   g_cursor[NN];
__device__ __align__(16) float g_dinv[NN];
__device__ __align__(16) float g_selfw[NN];
__device__ __align__(16) float g_Wp[DD * DD];       // folded weights (scale * W)
__device__ __align__(16) float g_cvec[DD];          // shift^T W  (pre-aggregation row constant)
__device__ __align__(16) float g_bias2[DD];         // raw layer bias b (post-aggregation)
__device__ __align__(16) float g_colsum[DD];
__device__ __align__(16) float g_colsumsq[DD];
__device__ __align__(16) float g_scale[DD];         // BN affine from previous layer
__device__ __align__(16) float g_shift[DD];

// ---------------- init: zero counts, unit scale, zero output ----------------
__global__ void init_kernel(float* out) {
    int i = blockIdx.x * blockDim.x + threadIdx.x;
    if (i < NN) g_counts[i] = 0;
    if (i < DD) { g_scale[i] = 1.0f; g_shift[i] = 0.0f; }
    if (i < GG * DD) out[i] = 0.0f;
}

// ---------------- degree count (in-degree of dst) ----------------
__global__ void count_kernel(const int* __restrict__ ei) {
    int e = blockIdx.x * blockDim.x + threadIdx.x;
    if (e >= EE) return;
    int d = ei[EE + e];
    atomicAdd(&g_counts[d], 1);
}

__global__ void deg_kernel() {
    int v = blockIdx.x * blockDim.x + threadIdx.x;
    if (v >= NN) return;
    float deg = 1.0f + (float)g_counts[v];
    g_dinv[v] = rsqrtf(deg);
    g_selfw[v] = 1.0f / deg;
}

// ---------------- single-block exclusive scan over counts ----------------
__global__ void scan_kernel() {
    __shared__ int s[1024];
    __shared__ int carry_s;
    int tid = threadIdx.x;
    if (tid == 0) carry_s = 0;
    __syncthreads();
    for (int base = 0; base < NN; base += 1024) {
        int i = base + tid;
        int v = (i < NN) ? g_counts[i] : 0;
        s[tid] = v;
        __syncthreads();
        for (int off = 1; off < 1024; off <<= 1) {
            int t = (tid >= off) ? s[tid - off] : 0;
            __syncthreads();
            s[tid] += t;
            __syncthreads();
        }
        int carry = carry_s;
        int inc = s[tid] + carry;
        if (i < NN) {
            g_rowptr[i + 1] = inc;
            g_cursor[i] = inc - v;   // exclusive prefix = row start
        }
        __syncthreads();
        if (tid == 1023) carry_s = inc;
        __syncthreads();
    }
    if (tid == 0) g_rowptr[0] = 0;
}

// ---------------- CSR fill (by dst), with symmetric-norm coefficient ----------------
__global__ void fill_kernel(const int* __restrict__ ei) {
    int e = blockIdx.x * blockDim.x + threadIdx.x;
    if (e >= EE) return;
    int s = ei[e];
    int d = ei[EE + e];
    float c = g_dinv[s] * g_dinv[d];
    int slot = atomicAdd(&g_cursor[d], 1);
    g_csr_src[slot] = s;
    g_csr_coef[slot] = c;
}

// ---------------- fold BN affine of previous layer into W; cvec = shift^T W ----------------
__global__ void fold_kernel(const float* __restrict__ W, const float* __restrict__ b) {
    int n = threadIdx.x;   // 0..127
    float acc = 0.0f;
    #pragma unroll 8
    for (int k = 0; k < DD; k++) {
        float w = W[k * DD + n];
        g_Wp[k * DD + n] = g_scale[k] * w;
        acc += g_shift[k] * w;
    }
    g_cvec[n]  = acc;      // added to every row of h (pre-aggregation)
    g_bias2[n] = b[n];     // added after aggregation (reference semantics)
    g_colsum[n] = 0.0f;
    g_colsumsq[n] = 0.0f;
}

// ---------------- GEMM: g_h = X @ g_Wp + cvec  (M=NN, N=K=128) ----------------
__global__ void gemm_kernel(const float* __restrict__ X) {
    __shared__ float As[32][132];   // [k][m], padded
    __shared__ float Bs[32][128];   // [k][n]
    int tid = threadIdx.x;
    int m0 = blockIdx.x * 128;
    int tx = tid & 15;      // 0..15 -> 8 cols each
    int ty = tid >> 4;      // 0..15 -> 8 rows each
    float acc[8][8];
    #pragma unroll
    for (int i = 0; i < 8; i++)
        #pragma unroll
        for (int j = 0; j < 8; j++) acc[i][j] = 0.0f;

    int lm  = tid >> 1;            // 0..127 row for X load
    int lk0 = (tid & 1) * 16;      // k-half
    int lkb = tid >> 3;            // 0..31 row for W load
    int ln0 = (tid & 7) * 16;      // n offset
    bool valid = (m0 + lm) < NN;

    for (int kk = 0; kk < DD; kk += 32) {
        const float* xr = X + (size_t)(m0 + lm) * DD + kk + lk0;
        #pragma unroll
        for (int j = 0; j < 16; j += 4) {
            float4 v = valid ? *(const float4*)(xr + j) : make_float4(0.f, 0.f, 0.f, 0.f);
            As[lk0 + j + 0][lm] = v.x;
            As[lk0 + j + 1][lm] = v.y;
            As[lk0 + j + 2][lm] = v.z;
            As[lk0 + j + 3][lm] = v.w;
        }
        const float* wr = g_Wp + (size_t)(kk + lkb) * DD + ln0;
        #pragma unroll
        for (int j = 0; j < 16; j += 4) {
            *(float4*)&Bs[lkb][ln0 + j] = *(const float4*)(wr + j);
        }
        __syncthreads();
        #pragma unroll
        for (int k = 0; k < 32; k++) {
            float a[8], bb[8];
            #pragma unroll
            for (int i = 0; i < 8; i++) a[i] = As[k][ty * 8 + i];
            #pragma unroll
            for (int i = 0; i < 8; i++) bb[i] = Bs[k][tx * 8 + i];
            #pragma unroll
            for (int i = 0; i < 8; i++)
                #pragma unroll
                for (int j = 0; j < 8; j++) acc[i][j] += a[i] * bb[j];
        }
        __syncthreads();
    }
    float4 cv0 = *(const float4*)(g_cvec + tx * 8);
    float4 cv1 = *(const float4*)(g_cvec + tx * 8 + 4);
    #pragma unroll
    for (int i = 0; i < 8; i++) {
        int m = m0 + ty * 8 + i;
        if (m < NN) {
            float4* hp = (float4*)(g_h + (size_t)m * DD + tx * 8);
            hp[0] = make_float4(acc[i][0] + cv0.x, acc[i][1] + cv0.y,
                                acc[i][2] + cv0.z, acc[i][3] + cv0.w);
            hp[1] = make_float4(acc[i][4] + cv1.x, acc[i][5] + cv1.y,
                                acc[i][6] + cv1.z, acc[i][7] + cv1.w);
        }
    }
}

// ---------------- aggregate + bias + relu + BN-stat accumulation ----------------
__global__ void agg_kernel() {
    int gtid = blockIdx.x * blockDim.x + threadIdx.x;
    int warp = gtid >> 5;
    int lane = threadIdx.x & 31;
    int nwarps = (gridDim.x * blockDim.x) >> 5;

    float4 bb = *(const float4*)(g_bias2 + lane * 4);
    float s0 = 0.f, s1 = 0.f, s2 = 0.f, s3 = 0.f;
    float q0 = 0.f, q1 = 0.f, q2 = 0.f, q3 = 0.f;

    for (int v = warp; v < NN; v += nwarps) {
        const float4* hv = (const float4*)(g_h + (size_t)v * DD) + lane;
        float4 h = *hv;
        float sw = g_selfw[v];
        float4 acc = make_float4(h.x * sw, h.y * sw, h.z * sw, h.w * sw);
        int e0 = g_rowptr[v], e1 = g_rowptr[v + 1];
        #pragma unroll 2
        for (int e = e0; e < e1; e++) {
            float c = g_csr_coef[e];
            int s = g_csr_src[e];
            float4 hs = *((const float4*)(g_h + (size_t)s * DD) + lane);
            acc.x += c * hs.x; acc.y += c * hs.y;
            acc.z += c * hs.z; acc.w += c * hs.w;
        }
        acc.x = fmaxf(acc.x + bb.x, 0.f);
        acc.y = fmaxf(acc.y + bb.y, 0.f);
        acc.z = fmaxf(acc.z + bb.z, 0.f);
        acc.w = fmaxf(acc.w + bb.w, 0.f);
        *((float4*)(g_act + (size_t)v * DD) + lane) = acc;
        s0 += acc.x; s1 += acc.y; s2 += acc.z; s3 += acc.w;
        q0 += acc.x * acc.x; q1 += acc.y * acc.y;
        q2 += acc.z * acc.z; q3 += acc.w * acc.w;
    }
    int c0 = lane * 4;
    atomicAdd(&g_colsum[c0 + 0], s0);
    atomicAdd(&g_colsum[c0 + 1], s1);
    atomicAdd(&g_colsum[c0 + 2], s2);
    atomicAdd(&g_colsum[c0 + 3], s3);
    atomicAdd(&g_colsumsq[c0 + 0], q0);
    atomicAdd(&g_colsumsq[c0 + 1], q1);
    atomicAdd(&g_colsumsq[c0 + 2], q2);
    atomicAdd(&g_colsumsq[c0 + 3], q3);
}

// ---------------- finalize BN affine for the next layer / pool ----------------
__global__ void stats_kernel(const float* __restrict__ gam, const float* __restrict__ bet) {
    int c = threadIdx.x;
    float mean = g_colsum[c] * (1.0f / (float)NN);
    float var = g_colsumsq[c] * (1.0f / (float)NN) - mean * mean;
    float rstd = rsqrtf(var + BN_EPS);
    float sc = gam[c] * rstd;
    g_scale[c] = sc;
    g_shift[c] = bet[c] - mean * sc;
}

// ---------------- pool: apply last BN affine, segment-sum over sorted batch ----------------
__global__ void pool_kernel(const int* __restrict__ batch, float* __restrict__ out) {
    int t = threadIdx.x;   // column 0..127
    int nb = gridDim.x;
    int per = (NN + nb - 1) / nb;
    int v0 = blockIdx.x * per;
    int v1 = min(NN, v0 + per);
    if (v0 >= v1) return;
    float sc = g_scale[t], sh = g_shift[t];
    float acc = 0.0f;
    int g = batch[v0];
    for (int v = v0; v < v1; v++) {
        int gv = batch[v];
        if (gv != g) {
            atomicAdd(&out[g * DD + t], acc);
            acc = 0.0f;
            g = gv;
        }
        acc += g_act[(size_t)v * DD + t] * sc + sh;
    }
    atomicAdd(&out[g * DD + t], acc);
}

// ---------------- launch ----------------
extern "C" void kernel_launch(void* const* d_in, const int* in_sizes, int n_in,
                              void* d_out, int out_size) {
    const float* x = (const float*)d_in[0];
    const int* ei = (const int*)d_in[1];      // int32
    const int* batch = (const int*)d_in[2];   // int32
    const float *W[4], *b[4], *gam[4], *bet[4];
    for (int i = 0; i < 4; i++) {
        W[i]   = (const float*)d_in[3 + 4 * i];
        b[i]   = (const float*)d_in[4 + 4 * i];
        gam[i] = (const float*)d_in[5 + 4 * i];
        bet[i] = (const float*)d_in[6 + 4 * i];
    }
    float* out = (float*)d_out;
    float* actp = nullptr;
    cudaGetSymbolAddress((void**)&actp, g_act);

    init_kernel<<<(NN + 255) / 256, 256>>>(out);
    count_kernel<<<(EE + 255) / 256, 256>>>(ei);
    deg_kernel<<<(NN + 255) / 256, 256>>>();
    scan_kernel<<<1, 1024>>>();
    fill_kernel<<<(EE + 255) / 256, 256>>>(ei);

    for (int L = 0; L < 4; L++) {
        fold_kernel<<<1, DD>>>(W[L], b[L]);
        gemm_kernel<<<(NN + 127) / 128, 256>>>(L == 0 ? x : actp);
        agg_kernel<<<592, 256>>>();
        stats_kernel<<<1, DD>>>(gam[L], bet[L]);
    }
    pool_kernel<<<256, DD>>>(batch, out);
}

// round 5
// speedup vs baseline: 1.0533x; 1.0533x over previous
#include <cuda_runtime.h>
#include <cuda_bf16.h>
#include <math.h>

#define NN 50000
#define EE 800000
#define GG 64
#define DD 128
#define BN_EPS 1e-5f

// ---------------- scratch (device globals; no allocation) ----------------
__device__ __align__(16) float g_h[NN * DD];        // post-GEMM features (= bn(x) @ W exactly)
__device__ __align__(16) float g_act[NN * DD];      // post-aggregate/relu activations
__device__ __align__(16) int   g_csr_src[EE];
__device__ __align__(16) float g_csr_coef[EE];
__device__ __align__(16) int   g_rowptr[NN + 1];
__device__ __align__(16) int   g_counts[NN];
__device__ __align__(16) int   g_cursor[NN];
__device__ __align__(16) float g_dinv[NN];
__device__ __align__(16) float g_selfw[NN];
__device__ __align__(16) float g_Wp[DD * DD];       // folded weights (scale * W)
__device__ __align__(16) float g_cvec[DD];          // shift^T W  (pre-aggregation row constant)
__device__ __align__(16) float g_bias2[DD];         // raw layer bias b (post-aggregation)
__device__ __align__(16) float g_colsum[DD];
__device__ __align__(16) float g_colsumsq[DD];
__device__ __align__(16) float g_scale[DD];         // BN affine from previous layer
__device__ __align__(16) float g_shift[DD];

// ---------------- packed f32x2 helpers (PTX ISA 8.6, sm_100+) ----------------
__device__ __forceinline__ unsigned long long pk2(float lo, float hi) {
    unsigned long long r;
    asm("mov.b64 %0, {%1, %2};" : "=l"(r) : "f"(lo), "f"(hi));
    return r;
}
__device__ __forceinline__ void upk2(unsigned long long v, float& lo, float& hi) {
    asm("mov.b64 {%0, %1}, %2;" : "=f"(lo), "=f"(hi) : "l"(v));
}
__device__ __forceinline__ unsigned long long fma2(unsigned long long a,
                                                   unsigned long long b,
                                                   unsigned long long c) {
    unsigned long long d;
    asm("fma.rn.f32x2 %0, %1, %2, %3;" : "=l"(d) : "l"(a), "l"(b), "l"(c));
    return d;
}

// ---------------- init ----------------
__global__ void init_kernel(float* out) {
    int i = blockIdx.x * blockDim.x + threadIdx.x;
    if (i < NN) g_counts[i] = 0;
    if (i < DD) {
        g_scale[i] = 1.0f; g_shift[i] = 0.0f;
        g_cvec[i] = 0.0f; g_colsum[i] = 0.0f; g_colsumsq[i] = 0.0f;
    }
    if (i < GG * DD) out[i] = 0.0f;
}

// ---------------- degree count (in-degree of dst) ----------------
__global__ void count_kernel(const int* __restrict__ ei) {
    int e = blockIdx.x * blockDim.x + threadIdx.x;
    if (e >= EE) return;
    atomicAdd(&g_counts[ei[EE + e]], 1);
}

__global__ void deg_kernel() {
    int v = blockIdx.x * blockDim.x + threadIdx.x;
    if (v >= NN) return;
    float deg = 1.0f + (float)g_counts[v];
    g_dinv[v] = rsqrtf(deg);
    g_selfw[v] = 1.0f / deg;
}

// ---------------- scan: per-thread sequential chunks + ONE block scan ----------------
#define CHUNK 49   // ceil(50000 / 1024)
__global__ void scan_kernel() {
    __shared__ int s[1024];
    int tid = threadIdx.x;
    int lo = tid * CHUNK;
    int hi = min(NN, lo + CHUNK);
    // pass 1: local sum
    int sum = 0;
    #pragma unroll 8
    for (int i = lo; i < hi; i++) sum += g_counts[i];
    s[tid] = sum;
    __syncthreads();
    // block inclusive scan over 1024 partials
    #pragma unroll
    for (int off = 1; off < 1024; off <<= 1) {
        int t = (tid >= off) ? s[tid - off] : 0;
        __syncthreads();
        s[tid] += t;
        __syncthreads();
    }
    int run = (tid > 0) ? s[tid - 1] : 0;   // exclusive prefix of this chunk
    // pass 2: replay, write rowptr (inclusive at i+1) and cursor (exclusive)
    for (int i = lo; i < hi; i++) {
        int v = g_counts[i];
        g_cursor[i] = run;
        run += v;
        g_rowptr[i + 1] = run;
    }
    if (tid == 0) g_rowptr[0] = 0;
}

// ---------------- CSR fill (by dst), with symmetric-norm coefficient ----------------
__global__ void fill_kernel(const int* __restrict__ ei) {
    int e = blockIdx.x * blockDim.x + threadIdx.x;
    if (e >= EE) return;
    int s = ei[e];
    int d = ei[EE + e];
    float c = g_dinv[s] * g_dinv[d];
    int slot = atomicAdd(&g_cursor[d], 1);
    g_csr_src[slot] = s;
    g_csr_coef[slot] = c;
}

// ---------------- fold (parallel): Wp = scale*W, cvec += shift^T W, bias2 = b ----------------
// g_cvec must be zero on entry (init for L1, stats_kernel for L2..L4).
__global__ void fold_kernel(const float* __restrict__ W, const float* __restrict__ b) {
    int idx = blockIdx.x * blockDim.x + threadIdx.x;   // 0..16383
    int k = idx >> 7;
    int n = idx & 127;
    float w = W[idx];
    g_Wp[idx] = g_scale[k] * w;
    float contrib = g_shift[k] * w;
    if (contrib != 0.0f) atomicAdd(&g_cvec[n], contrib);
    if (idx < DD) g_bias2[idx] = b[idx];
}

// ---------------- GEMM: g_h = X @ g_Wp + cvec  (packed f32x2 FMA) ----------------
__global__ void gemm_kernel(const float* __restrict__ X) {
    __shared__ float As[32][132];   // [k][m], padded
    __shared__ float Bs[32][128];   // [k][n]
    int tid = threadIdx.x;
    int m0 = blockIdx.x * 128;
    int tx = tid & 15;      // 0..15 -> 8 output cols each (4 packed pairs)
    int ty = tid >> 4;      // 0..15 -> 8 output rows each
    unsigned long long acc2[8][4];
    #pragma unroll
    for (int i = 0; i < 8; i++)
        #pragma unroll
        for (int j = 0; j < 4; j++) acc2[i][j] = 0ULL;   // {0.0f, 0.0f}

    int lm  = tid >> 1;            // 0..127 row for X load
    int lk0 = (tid & 1) * 16;      // k-half
    int lkb = tid >> 3;            // 0..31 row for W load
    int ln0 = (tid & 7) * 16;      // n offset
    bool valid = (m0 + lm) < NN;

    for (int kk = 0; kk < DD; kk += 32) {
        const float* xr = X + (size_t)(m0 + lm) * DD + kk + lk0;
        #pragma unroll
        for (int j = 0; j < 16; j += 4) {
            float4 v = valid ? *(const float4*)(xr + j) : make_float4(0.f, 0.f, 0.f, 0.f);
            As[lk0 + j + 0][lm] = v.x;
            As[lk0 + j + 1][lm] = v.y;
            As[lk0 + j + 2][lm] = v.z;
            As[lk0 + j + 3][lm] = v.w;
        }
        const float* wr = g_Wp + (size_t)(kk + lkb) * DD + ln0;
        #pragma unroll
        for (int j = 0; j < 16; j += 4) {
            *(float4*)&Bs[lkb][ln0 + j] = *(const float4*)(wr + j);
        }
        __syncthreads();
        #pragma unroll
        for (int k = 0; k < 32; k++) {
            // B pairs: 8 contiguous floats -> 4 b64 operands
            unsigned long long b2[4];
            const float2* bp = (const float2*)&Bs[k][tx * 8];
            #pragma unroll
            for (int j = 0; j < 4; j++) {
                float2 f = bp[j];
                b2[j] = pk2(f.x, f.y);
            }
            #pragma unroll
            for (int i = 0; i < 8; i++) {
                float a = As[k][ty * 8 + i];
                unsigned long long a2 = pk2(a, a);
                #pragma unroll
                for (int j = 0; j < 4; j++)
                    acc2[i][j] = fma2(a2, b2[j], acc2[i][j]);
            }
        }
        __syncthreads();
    }
    float4 cv0 = *(const float4*)(g_cvec + tx * 8);
    float4 cv1 = *(const float4*)(g_cvec + tx * 8 + 4);
    #pragma unroll
    for (int i = 0; i < 8; i++) {
        int m = m0 + ty * 8 + i;
        if (m < NN) {
            float r[8];
            #pragma unroll
            for (int j = 0; j < 4; j++) upk2(acc2[i][j], r[2 * j], r[2 * j + 1]);
            float4* hp = (float4*)(g_h + (size_t)m * DD + tx * 8);
            hp[0] = make_float4(r[0] + cv0.x, r[1] + cv0.y, r[2] + cv0.z, r[3] + cv0.w);
            hp[1] = make_float4(r[4] + cv1.x, r[5] + cv1.y, r[6] + cv1.z, r[7] + cv1.w);
        }
    }
}

// ---------------- aggregate + bias + relu + BN-stat accumulation ----------------
__global__ void agg_kernel() {
    int gtid = blockIdx.x * blockDim.x + threadIdx.x;
    int warp = gtid >> 5;
    int lane = threadIdx.x & 31;
    int nwarps = (gridDim.x * blockDim.x) >> 5;

    float4 bb = *(const float4*)(g_bias2 + lane * 4);
    float s0 = 0.f, s1 = 0.f, s2 = 0.f, s3 = 0.f;
    float q0 = 0.f, q1 = 0.f, q2 = 0.f, q3 = 0.f;

    for (int v = warp; v < NN; v += nwarps) {
        const float4* hv = (const float4*)(g_h + (size_t)v * DD) + lane;
        float4 h = *hv;
        float sw = g_selfw[v];
        float4 acc = make_float4(h.x * sw, h.y * sw, h.z * sw, h.w * sw);
        int e0 = g_rowptr[v], e1 = g_rowptr[v + 1];
        #pragma unroll 2
        for (int e = e0; e < e1; e++) {
            float c = g_csr_coef[e];
            int s = g_csr_src[e];
            float4 hs = *((const float4*)(g_h + (size_t)s * DD) + lane);
            acc.x += c * hs.x; acc.y += c * hs.y;
            acc.z += c * hs.z; acc.w += c * hs.w;
        }
        acc.x = fmaxf(acc.x + bb.x, 0.f);
        acc.y = fmaxf(acc.y + bb.y, 0.f);
        acc.z = fmaxf(acc.z + bb.z, 0.f);
        acc.w = fmaxf(acc.w + bb.w, 0.f);
        *((float4*)(g_act + (size_t)v * DD) + lane) = acc;
        s0 += acc.x; s1 += acc.y; s2 += acc.z; s3 += acc.w;
        q0 += acc.x * acc.x; q1 += acc.y * acc.y;
        q2 += acc.z * acc.z; q3 += acc.w * acc.w;
    }
    int c0 = lane * 4;
    atomicAdd(&g_colsum[c0 + 0], s0);
    atomicAdd(&g_colsum[c0 + 1], s1);
    atomicAdd(&g_colsum[c0 + 2], s2);
    atomicAdd(&g_colsum[c0 + 3], s3);
    atomicAdd(&g_colsumsq[c0 + 0], q0);
    atomicAdd(&g_colsumsq[c0 + 1], q1);
    atomicAdd(&g_colsumsq[c0 + 2], q2);
    atomicAdd(&g_colsumsq[c0 + 3], q3);
}

// ---------------- finalize BN affine; re-zero accumulators for next layer ----------------
__global__ void stats_kernel(const float* __restrict__ gam, const float* __restrict__ bet) {
    int c = threadIdx.x;
    float mean = g_colsum[c] * (1.0f / (float)NN);
    float var = g_colsumsq[c] * (1.0f / (float)NN) - mean * mean;
    float rstd = rsqrtf(var + BN_EPS);
    float sc = gam[c] * rstd;
    g_scale[c] = sc;
    g_shift[c] = bet[c] - mean * sc;
    g_colsum[c] = 0.0f;
    g_colsumsq[c] = 0.0f;
    g_cvec[c] = 0.0f;
}

// ---------------- pool: apply last BN affine, segment-sum over sorted batch ----------------
__global__ void pool_kernel(const int* __restrict__ batch, float* __restrict__ out) {
    int t = threadIdx.x;   // column 0..127
    int nb = gridDim.x;
    int per = (NN + nb - 1) / nb;
    int v0 = blockIdx.x * per;
    int v1 = min(NN, v0 + per);
    if (v0 >= v1) return;
    float sc = g_scale[t], sh = g_shift[t];
    float acc = 0.0f;
    int g = batch[v0];
    for (int v = v0; v < v1; v++) {
        int gv = batch[v];
        if (gv != g) {
            atomicAdd(&out[g * DD + t], acc);
            acc = 0.0f;
            g = gv;
        }
        acc += g_act[(size_t)v * DD + t] * sc + sh;
    }
    atomicAdd(&out[g * DD + t], acc);
}

// ---------------- launch ----------------
extern "C" void kernel_launch(void* const* d_in, const int* in_sizes, int n_in,
                              void* d_out, int out_size) {
    const float* x = (const float*)d_in[0];
    const int* ei = (const int*)d_in[1];      // int32
    const int* batch = (const int*)d_in[2];   // int32
    const float *W[4], *b[4], *gam[4], *bet[4];
    for (int i = 0; i < 4; i++) {
        W[i]   = (const float*)d_in[3 + 4 * i];
        b[i]   = (const float*)d_in[4 + 4 * i];
        gam[i] = (const float*)d_in[5 + 4 * i];
        bet[i] = (const float*)d_in[6 + 4 * i];
    }
    float* out = (float*)d_out;
    float* actp = nullptr;
    cudaGetSymbolAddress((void**)&actp, g_act);

    init_kernel<<<(NN + 255) / 256, 256>>>(out);
    count_kernel<<<(EE + 255) / 256, 256>>>(ei);
    deg_kernel<<<(NN + 255) / 256, 256>>>();
    scan_kernel<<<1, 1024>>>();
    fill_kernel<<<(EE + 255) / 256, 256>>>(ei);

    for (int L = 0; L < 4; L++) {
        fold_kernel<<<64, 256>>>(W[L], b[L]);
        gemm_kernel<<<(NN + 127) / 128, 256>>>(L == 0 ? x : actp);
        agg_kernel<<<592, 256>>>();
        stats_kernel<<<1, DD>>>(gam[L], bet[L]);
    }
    pool_kernel<<<256, DD>>>(batch, out);
}

// round 6
// speedup vs baseline: 1.1500x; 1.0918x over previous
#include <cuda_runtime.h>
#include <cuda_bf16.h>
#include <math.h>

#define NN 50000
#define EE 800000
#define GG 64
#define DD 128
#define BN_EPS 1e-5f
#define NB_SCAN 196   // ceil(50000/256)

// ---------------- scratch (device globals; no allocation) ----------------
__device__ __align__(16) float g_h[NN * DD];        // post-GEMM features (= bn(x) @ W exactly)
__device__ __align__(16) float g_act[NN * DD];      // post-aggregate/relu activations
__device__ __align__(16) int   g_csr_src[EE];
__device__ __align__(16) float g_csr_coef[EE];
__device__ __align__(16) int   g_rowptr[NN + 1];
__device__ __align__(16) int   g_counts[NN];
__device__ __align__(16) int   g_cursor[NN];
__device__ __align__(16) float g_dinv[NN];
__device__ __align__(16) float g_selfw[NN];
__device__ __align__(16) int   g_bsum[NB_SCAN];
__device__ __align__(16) int   g_boff[NB_SCAN];
__device__ __align__(16) float g_Wp[DD * DD];       // folded weights (scale * W)
__device__ __align__(16) float g_cvec[DD];          // shift^T W  (pre-aggregation row constant)
__device__ __align__(16) float g_bias2[DD];         // raw layer bias b (post-aggregation)
__device__ __align__(16) float g_colsum[DD];
__device__ __align__(16) float g_colsumsq[DD];
__device__ __align__(16) float g_scale[DD];         // BN affine from previous layer
__device__ __align__(16) float g_shift[DD];

// ---------------- packed f32x2 helpers (PTX ISA 8.6, sm_100+) ----------------
__device__ __forceinline__ unsigned long long pk2(float lo, float hi) {
    unsigned long long r;
    asm("mov.b64 %0, {%1, %2};" : "=l"(r) : "f"(lo), "f"(hi));
    return r;
}
__device__ __forceinline__ void upk2(unsigned long long v, float& lo, float& hi) {
    asm("mov.b64 {%0, %1}, %2;" : "=f"(lo), "=f"(hi) : "l"(v));
}
__device__ __forceinline__ unsigned long long fma2(unsigned long long a,
                                                   unsigned long long b,
                                                   unsigned long long c) {
    unsigned long long d;
    asm("fma.rn.f32x2 %0, %1, %2, %3;" : "=l"(d) : "l"(a), "l"(b), "l"(c));
    return d;
}

// ---------------- init ----------------
__global__ void init_kernel(float* out) {
    int i = blockIdx.x * blockDim.x + threadIdx.x;
    if (i < NN) g_counts[i] = 0;
    if (i < DD) {
        g_scale[i] = 1.0f; g_shift[i] = 0.0f;
        g_cvec[i] = 0.0f; g_colsum[i] = 0.0f; g_colsumsq[i] = 0.0f;
    }
    if (i < GG * DD) out[i] = 0.0f;
}

// ---------------- degree count (in-degree of dst) ----------------
__global__ void count_kernel(const int* __restrict__ ei) {
    int e = blockIdx.x * blockDim.x + threadIdx.x;
    if (e >= EE) return;
    atomicAdd(&g_counts[ei[EE + e]], 1);
}

__global__ void deg_kernel() {
    int v = blockIdx.x * blockDim.x + threadIdx.x;
    if (v >= NN) return;
    float deg = 1.0f + (float)g_counts[v];
    g_dinv[v] = rsqrtf(deg);
    g_selfw[v] = 1.0f / deg;
}

// ---------------- 3-phase coalesced scan ----------------
__device__ __forceinline__ int block_incl_scan_256(int v, int* ws) {
    int lane = threadIdx.x & 31, wid = threadIdx.x >> 5;
    int x = v;
    #pragma unroll
    for (int off = 1; off < 32; off <<= 1) {
        int t = __shfl_up_sync(0xFFFFFFFFu, x, off);
        if (lane >= off) x += t;
    }
    if (lane == 31) ws[wid] = x;
    __syncthreads();
    if (threadIdx.x < 8) {
        int y = ws[threadIdx.x];
        #pragma unroll
        for (int off = 1; off < 8; off <<= 1) {
            int t = __shfl_up_sync(0xFFu, y, off);
            if ((int)threadIdx.x >= off) y += t;
        }
        ws[threadIdx.x] = y;
    }
    __syncthreads();
    return x + ((wid > 0) ? ws[wid - 1] : 0);
}

__global__ void scanA_kernel() {
    __shared__ int ws[8];
    int i = blockIdx.x * 256 + threadIdx.x;
    int v = (i < NN) ? g_counts[i] : 0;
    int incl = block_incl_scan_256(v, ws);
    if (i < NN) {
        g_rowptr[i + 1] = incl;       // local inclusive (offset added in scanC)
        g_cursor[i] = incl - v;       // local exclusive
    }
    if (threadIdx.x == 255) g_bsum[blockIdx.x] = incl;   // block total
}

__global__ void scanB_kernel() {
    __shared__ int ws[8];
    int b = threadIdx.x;
    int v = (b < NB_SCAN) ? g_bsum[b] : 0;
    int incl = block_incl_scan_256(v, ws);
    if (b < NB_SCAN) g_boff[b] = incl - v;   // exclusive block offset
    if (b == 0) g_rowptr[0] = 0;
}

__global__ void scanC_kernel() {
    int i = blockIdx.x * 256 + threadIdx.x;
    if (i >= NN) return;
    int off = g_boff[blockIdx.x];
    g_rowptr[i + 1] += off;
    g_cursor[i] += off;
}

// ---------------- CSR fill (by dst), with symmetric-norm coefficient ----------------
__global__ void fill_kernel(const int* __restrict__ ei) {
    int e = blockIdx.x * blockDim.x + threadIdx.x;
    if (e >= EE) return;
    int s = ei[e];
    int d = ei[EE + e];
    float c = g_dinv[s] * g_dinv[d];
    int slot = atomicAdd(&g_cursor[d], 1);
    g_csr_src[slot] = s;
    g_csr_coef[slot] = c;
}

// ---------------- fold (parallel): Wp = scale*W, cvec += shift^T W, bias2 = b ----------------
__global__ void fold_kernel(const float* __restrict__ W, const float* __restrict__ b) {
    int idx = blockIdx.x * blockDim.x + threadIdx.x;   // 0..16383
    int k = idx >> 7;
    int n = idx & 127;
    float w = W[idx];
    g_Wp[idx] = g_scale[k] * w;
    float contrib = g_shift[k] * w;
    if (contrib != 0.0f) atomicAdd(&g_cvec[n], contrib);
    if (idx < DD) g_bias2[idx] = b[idx];
}

// ---------------- GEMM: g_h = X @ g_Wp + cvec  (f32x2 FMA, LDS.128 operands) ----------------
__global__ void gemm_kernel(const float* __restrict__ X) {
    __shared__ float As[32][132];   // [k][m], padded (132 floats = 16B-aligned rows)
    __shared__ float Bs[32][128];   // [k][n]
    int tid = threadIdx.x;
    int m0 = blockIdx.x * 128;
    int tx = tid & 15;      // 8 output cols (4 packed pairs)
    int ty = tid >> 4;      // 8 output rows
    unsigned long long acc2[8][4];
    #pragma unroll
    for (int i = 0; i < 8; i++)
        #pragma unroll
        for (int j = 0; j < 4; j++) acc2[i][j] = 0ULL;

    int lm  = tid >> 1;            // 0..127 row for X load
    int lk0 = (tid & 1) * 16;      // k-half
    int lkb = tid >> 3;            // 0..31 row for W load
    int ln0 = (tid & 7) * 16;      // n offset
    bool valid = (m0 + lm) < NN;

    for (int kk = 0; kk < DD; kk += 32) {
        const float* xr = X + (size_t)(m0 + lm) * DD + kk + lk0;
        #pragma unroll
        for (int j = 0; j < 16; j += 4) {
            float4 v = valid ? *(const float4*)(xr + j) : make_float4(0.f, 0.f, 0.f, 0.f);
            As[lk0 + j + 0][lm] = v.x;
            As[lk0 + j + 1][lm] = v.y;
            As[lk0 + j + 2][lm] = v.z;
            As[lk0 + j + 3][lm] = v.w;
        }
        const float* wr = g_Wp + (size_t)(kk + lkb) * DD + ln0;
        #pragma unroll
        for (int j = 0; j < 16; j += 4) {
            *(float4*)&Bs[lkb][ln0 + j] = *(const float4*)(wr + j);
        }
        __syncthreads();
        #pragma unroll
        for (int k = 0; k < 32; k++) {
            // 2x LDS.128 for B, 2x LDS.128 for A (both contiguous in shared)
            float4 bv0 = *(const float4*)&Bs[k][tx * 8];
            float4 bv1 = *(const float4*)&Bs[k][tx * 8 + 4];
            float4 av0 = *(const float4*)&As[k][ty * 8];
            float4 av1 = *(const float4*)&As[k][ty * 8 + 4];
            unsigned long long b2[4];
            b2[0] = pk2(bv0.x, bv0.y); b2[1] = pk2(bv0.z, bv0.w);
            b2[2] = pk2(bv1.x, bv1.y); b2[3] = pk2(bv1.z, bv1.w);
            float av[8] = {av0.x, av0.y, av0.z, av0.w, av1.x, av1.y, av1.z, av1.w};
            #pragma unroll
            for (int i = 0; i < 8; i++) {
                unsigned long long a2 = pk2(av[i], av[i]);
                #pragma unroll
                for (int j = 0; j < 4; j++)
                    acc2[i][j] = fma2(a2, b2[j], acc2[i][j]);
            }
        }
        __syncthreads();
    }
    float4 cv0 = *(const float4*)(g_cvec + tx * 8);
    float4 cv1 = *(const float4*)(g_cvec + tx * 8 + 4);
    #pragma unroll
    for (int i = 0; i < 8; i++) {
        int m = m0 + ty * 8 + i;
        if (m < NN) {
            float r[8];
            #pragma unroll
            for (int j = 0; j < 4; j++) upk2(acc2[i][j], r[2 * j], r[2 * j + 1]);
            float4* hp = (float4*)(g_h + (size_t)m * DD + tx * 8);
            hp[0] = make_float4(r[0] + cv0.x, r[1] + cv0.y, r[2] + cv0.z, r[3] + cv0.w);
            hp[1] = make_float4(r[4] + cv1.x, r[5] + cv1.y, r[6] + cv1.z, r[7] + cv1.w);
        }
    }
}

// ---------------- aggregate + bias + relu + BN-stat accumulation ----------------
__global__ void agg_kernel() {
    int gtid = blockIdx.x * blockDim.x + threadIdx.x;
    int warp = gtid >> 5;
    int lane = threadIdx.x & 31;
    int nwarps = (gridDim.x * blockDim.x) >> 5;

    float4 bb = *(const float4*)(g_bias2 + lane * 4);
    float s0 = 0.f, s1 = 0.f, s2 = 0.f, s3 = 0.f;
    float q0 = 0.f, q1 = 0.f, q2 = 0.f, q3 = 0.f;

    for (int v = warp; v < NN; v += nwarps) {
        const float4* hv = (const float4*)(g_h + (size_t)v * DD) + lane;
        float4 h = *hv;
        float sw = g_selfw[v];
        float4 acc = make_float4(h.x * sw, h.y * sw, h.z * sw, h.w * sw);
        int e0 = g_rowptr[v], e1 = g_rowptr[v + 1];
        #pragma unroll 2
        for (int e = e0; e < e1; e++) {
            float c = g_csr_coef[e];
            int s = g_csr_src[e];
            float4 hs = *((const float4*)(g_h + (size_t)s * DD) + lane);
            acc.x += c * hs.x; acc.y += c * hs.y;
            acc.z += c * hs.z; acc.w += c * hs.w;
        }
        acc.x = fmaxf(acc.x + bb.x, 0.f);
        acc.y = fmaxf(acc.y + bb.y, 0.f);
        acc.z = fmaxf(acc.z + bb.z, 0.f);
        acc.w = fmaxf(acc.w + bb.w, 0.f);
        *((float4*)(g_act + (size_t)v * DD) + lane) = acc;
        s0 += acc.x; s1 += acc.y; s2 += acc.z; s3 += acc.w;
        q0 += acc.x * acc.x; q1 += acc.y * acc.y;
        q2 += acc.z * acc.z; q3 += acc.w * acc.w;
    }
    int c0 = lane * 4;
    atomicAdd(&g_colsum[c0 + 0], s0);
    atomicAdd(&g_colsum[c0 + 1], s1);
    atomicAdd(&g_colsum[c0 + 2], s2);
    atomicAdd(&g_colsum[c0 + 3], s3);
    atomicAdd(&g_colsumsq[c0 + 0], q0);
    atomicAdd(&g_colsumsq[c0 + 1], q1);
    atomicAdd(&g_colsumsq[c0 + 2], q2);
    atomicAdd(&g_colsumsq[c0 + 3], q3);
}

// ---------------- finalize BN affine; re-zero accumulators for next layer ----------------
__global__ void stats_kernel(const float* __restrict__ gam, const float* __restrict__ bet) {
    int c = threadIdx.x;
    float mean = g_colsum[c] * (1.0f / (float)NN);
    float var = g_colsumsq[c] * (1.0f / (float)NN) - mean * mean;
    float rstd = rsqrtf(var + BN_EPS);
    float sc = gam[c] * rstd;
    g_scale[c] = sc;
    g_shift[c] = bet[c] - mean * sc;
    g_colsum[c] = 0.0f;
    g_colsumsq[c] = 0.0f;
    g_cvec[c] = 0.0f;
}

// ---------------- pool: apply last BN affine, segment-sum over sorted batch ----------------
__global__ void pool_kernel(const int* __restrict__ batch, float* __restrict__ out) {
    int t = threadIdx.x;   // column 0..127
    int nb = gridDim.x;
    int per = (NN + nb - 1) / nb;
    int v0 = blockIdx.x * per;
    int v1 = min(NN, v0 + per);
    if (v0 >= v1) return;
    float sc = g_scale[t], sh = g_shift[t];
    float acc = 0.0f;
    int g = batch[v0];
    for (int v = v0; v < v1; v++) {
        int gv = batch[v];
        if (gv != g) {
            atomicAdd(&out[g * DD + t], acc);
            acc = 0.0f;
            g = gv;
        }
        acc += g_act[(size_t)v * DD + t] * sc + sh;
    }
    atomicAdd(&out[g * DD + t], acc);
}

// ---------------- launch ----------------
extern "C" void kernel_launch(void* const* d_in, const int* in_sizes, int n_in,
                              void* d_out, int out_size) {
    const float* x = (const float*)d_in[0];
    const int* ei = (const int*)d_in[1];      // int32
    const int* batch = (const int*)d_in[2];   // int32
    const float *W[4], *b[4], *gam[4], *bet[4];
    for (int i = 0; i < 4; i++) {
        W[i]   = (const float*)d_in[3 + 4 * i];
        b[i]   = (const float*)d_in[4 + 4 * i];
        gam[i] = (const float*)d_in[5 + 4 * i];
        bet[i] = (const float*)d_in[6 + 4 * i];
    }
    float* out = (float*)d_out;
    float* actp = nullptr;
    cudaGetSymbolAddress((void**)&actp, g_act);

    init_kernel<<<(NN + 255) / 256, 256>>>(out);
    count_kernel<<<(EE + 255) / 256, 256>>>(ei);
    deg_kernel<<<(NN + 255) / 256, 256>>>();
    scanA_kernel<<<NB_SCAN, 256>>>();
    scanB_kernel<<<1, 256>>>();
    scanC_kernel<<<NB_SCAN, 256>>>();
    fill_kernel<<<(EE + 255) / 256, 256>>>(ei);

    for (int L = 0; L < 4; L++) {
        fold_kernel<<<64, 256>>>(W[L], b[L]);
        gemm_kernel<<<(NN + 127) / 128, 256>>>(L == 0 ? x : actp);
        agg_kernel<<<592, 256>>>();
        stats_kernel<<<1, DD>>>(gam[L], bet[L]);
    }
    pool_kernel<<<256, DD>>>(batch, out);
}

// round 7
// speedup vs baseline: 1.2602x; 1.0959x over previous
#include <cuda_runtime.h>
#include <cuda_bf16.h>
#include <math.h>

#define NN 50000
#define EE 800000
#define GG 64
#define DD 128
#define BN_EPS 1e-5f
#define NB_SCAN 196   // ceil(50000/256)

// ---------------- scratch (device globals; no allocation) ----------------
__device__ __align__(16) float g_h[NN * DD];        // post-GEMM features (= bn(x) @ W exactly)
__device__ __align__(16) float g_act[NN * DD];      // post-aggregate/relu activations
__device__ __align__(16) int   g_csr_src[EE];
__device__ __align__(16) float g_csr_coef[EE];
__device__ __align__(16) int   g_rowptr[NN + 1];
__device__ __align__(16) int   g_counts[NN];
__device__ __align__(16) int   g_cursor[NN];
__device__ __align__(16) float g_dinv[NN];
__device__ __align__(16) float g_selfw[NN];
__device__ __align__(16) int   g_bsum[NB_SCAN];
__device__ __align__(16) int   g_boff[NB_SCAN];
__device__ __align__(16) float g_Wp[DD * DD];       // folded weights (scale * W)
__device__ __align__(16) float g_cvec[DD];          // shift^T W  (pre-aggregation row constant)
__device__ __align__(16) float g_bias2[DD];         // raw layer bias b (post-aggregation)
__device__ __align__(16) float g_colsum[DD];
__device__ __align__(16) float g_colsumsq[DD];
__device__ __align__(16) float g_scale[DD];         // BN affine from previous layer
__device__ __align__(16) float g_shift[DD];

// ---------------- packed f32x2 helpers (PTX ISA 8.6, sm_100+) ----------------
__device__ __forceinline__ unsigned long long pk2(float lo, float hi) {
    unsigned long long r;
    asm("mov.b64 %0, {%1, %2};" : "=l"(r) : "f"(lo), "f"(hi));
    return r;
}
__device__ __forceinline__ void upk2(unsigned long long v, float& lo, float& hi) {
    asm("mov.b64 {%0, %1}, %2;" : "=f"(lo), "=f"(hi) : "l"(v));
}
__device__ __forceinline__ unsigned long long fma2(unsigned long long a,
                                                   unsigned long long b,
                                                   unsigned long long c) {
    unsigned long long d;
    asm("fma.rn.f32x2 %0, %1, %2, %3;" : "=l"(d) : "l"(a), "l"(b), "l"(c));
    return d;
}

// ---------------- init ----------------
__global__ void init_kernel(float* out) {
    int i = blockIdx.x * blockDim.x + threadIdx.x;
    if (i < NN) g_counts[i] = 0;
    if (i < DD) {
        g_scale[i] = 1.0f; g_shift[i] = 0.0f;
        g_cvec[i] = 0.0f; g_colsum[i] = 0.0f; g_colsumsq[i] = 0.0f;
    }
    if (i < GG * DD) out[i] = 0.0f;
}

// ---------------- degree count (in-degree of dst) ----------------
__global__ void count_kernel(const int* __restrict__ ei) {
    int e = blockIdx.x * blockDim.x + threadIdx.x;
    if (e >= EE) return;
    atomicAdd(&g_counts[ei[EE + e]], 1);
}

__global__ void deg_kernel() {
    int v = blockIdx.x * blockDim.x + threadIdx.x;
    if (v >= NN) return;
    float deg = 1.0f + (float)g_counts[v];
    g_dinv[v] = rsqrtf(deg);
    g_selfw[v] = 1.0f / deg;
}

// ---------------- 3-phase coalesced scan ----------------
__device__ __forceinline__ int block_incl_scan_256(int v, int* ws) {
    int lane = threadIdx.x & 31, wid = threadIdx.x >> 5;
    int x = v;
    #pragma unroll
    for (int off = 1; off < 32; off <<= 1) {
        int t = __shfl_up_sync(0xFFFFFFFFu, x, off);
        if (lane >= off) x += t;
    }
    if (lane == 31) ws[wid] = x;
    __syncthreads();
    if (threadIdx.x < 8) {
        int y = ws[threadIdx.x];
        #pragma unroll
        for (int off = 1; off < 8; off <<= 1) {
            int t = __shfl_up_sync(0xFFu, y, off);
            if ((int)threadIdx.x >= off) y += t;
        }
        ws[threadIdx.x] = y;
    }
    __syncthreads();
    return x + ((wid > 0) ? ws[wid - 1] : 0);
}

__global__ void scanA_kernel() {
    __shared__ int ws[8];
    int i = blockIdx.x * 256 + threadIdx.x;
    int v = (i < NN) ? g_counts[i] : 0;
    int incl = block_incl_scan_256(v, ws);
    if (i < NN) {
        g_rowptr[i + 1] = incl;       // local inclusive (offset added in scanC)
        g_cursor[i] = incl - v;       // local exclusive
    }
    if (threadIdx.x == 255) g_bsum[blockIdx.x] = incl;   // block total
}

__global__ void scanB_kernel() {
    __shared__ int ws[8];
    int b = threadIdx.x;
    int v = (b < NB_SCAN) ? g_bsum[b] : 0;
    int incl = block_incl_scan_256(v, ws);
    if (b < NB_SCAN) g_boff[b] = incl - v;   // exclusive block offset
    if (b == 0) g_rowptr[0] = 0;
}

__global__ void scanC_kernel() {
    int i = blockIdx.x * 256 + threadIdx.x;
    if (i >= NN) return;
    int off = g_boff[blockIdx.x];
    g_rowptr[i + 1] += off;
    g_cursor[i] += off;
}

// ---------------- CSR fill (by dst), with symmetric-norm coefficient ----------------
__global__ void fill_kernel(const int* __restrict__ ei) {
    int e = blockIdx.x * blockDim.x + threadIdx.x;
    if (e >= EE) return;
    int s = ei[e];
    int d = ei[EE + e];
    float c = g_dinv[s] * g_dinv[d];
    int slot = atomicAdd(&g_cursor[d], 1);
    g_csr_src[slot] = s;
    g_csr_coef[slot] = c;
}

// ---------------- fold (parallel): Wp = scale*W, cvec += shift^T W, bias2 = b ----------------
__global__ void fold_kernel(const float* __restrict__ W, const float* __restrict__ b) {
    int idx = blockIdx.x * blockDim.x + threadIdx.x;   // 0..16383
    int k = idx >> 7;
    int n = idx & 127;
    float w = W[idx];
    g_Wp[idx] = g_scale[k] * w;
    float contrib = g_shift[k] * w;
    if (contrib != 0.0f) atomicAdd(&g_cvec[n], contrib);
    if (idx < DD) g_bias2[idx] = b[idx];
}

// ---------------- GEMM: g_h = X @ g_Wp + cvec  (f32x2 FMA) ----------------
__global__ void __launch_bounds__(256, 2) gemm_kernel(const float* __restrict__ X) {
    __shared__ float As[32][132];   // [k][m], padded
    __shared__ float Bs[32][128];   // [k][n]
    int tid = threadIdx.x;
    int m0 = blockIdx.x * 128;
    int tx = tid & 15;      // 8 output cols (4 packed pairs)
    int ty = tid >> 4;      // 8 output rows
    unsigned long long acc2[8][4];
    #pragma unroll
    for (int i = 0; i < 8; i++)
        #pragma unroll
        for (int j = 0; j < 4; j++) acc2[i][j] = 0ULL;

    int lm  = tid >> 1;            // 0..127 row for X load
    int lk0 = (tid & 1) * 16;      // k-half
    int lkb = tid >> 3;            // 0..31 row for W load
    int ln0 = (tid & 7) * 16;      // n offset
    bool valid = (m0 + lm) < NN;

    for (int kk = 0; kk < DD; kk += 32) {
        const float* xr = X + (size_t)(m0 + lm) * DD + kk + lk0;
        #pragma unroll
        for (int j = 0; j < 16; j += 4) {
            float4 v = valid ? *(const float4*)(xr + j) : make_float4(0.f, 0.f, 0.f, 0.f);
            As[lk0 + j + 0][lm] = v.x;
            As[lk0 + j + 1][lm] = v.y;
            As[lk0 + j + 2][lm] = v.z;
            As[lk0 + j + 3][lm] = v.w;
        }
        const float* wr = g_Wp + (size_t)(kk + lkb) * DD + ln0;
        #pragma unroll
        for (int j = 0; j < 16; j += 4) {
            *(float4*)&Bs[lkb][ln0 + j] = *(const float4*)(wr + j);
        }
        __syncthreads();
        #pragma unroll
        for (int k = 0; k < 32; k++) {
            // B pairs read directly as 64-bit lanes (no pack movs)
            ulonglong2 bq0 = *(const ulonglong2*)&Bs[k][tx * 8];
            ulonglong2 bq1 = *(const ulonglong2*)&Bs[k][tx * 8 + 4];
            float4 av0 = *(const float4*)&As[k][ty * 8];
            float4 av1 = *(const float4*)&As[k][ty * 8 + 4];
            float av[8] = {av0.x, av0.y, av0.z, av0.w, av1.x, av1.y, av1.z, av1.w};
            #pragma unroll
            for (int i = 0; i < 8; i++) {
                unsigned long long a2 = pk2(av[i], av[i]);
                acc2[i][0] = fma2(a2, bq0.x, acc2[i][0]);
                acc2[i][1] = fma2(a2, bq0.y, acc2[i][1]);
                acc2[i][2] = fma2(a2, bq1.x, acc2[i][2]);
                acc2[i][3] = fma2(a2, bq1.y, acc2[i][3]);
            }
        }
        __syncthreads();
    }
    float4 cv0 = *(const float4*)(g_cvec + tx * 8);
    float4 cv1 = *(const float4*)(g_cvec + tx * 8 + 4);
    #pragma unroll
    for (int i = 0; i < 8; i++) {
        int m = m0 + ty * 8 + i;
        if (m < NN) {
            float r[8];
            #pragma unroll
            for (int j = 0; j < 4; j++) upk2(acc2[i][j], r[2 * j], r[2 * j + 1]);
            float4* hp = (float4*)(g_h + (size_t)m * DD + tx * 8);
            hp[0] = make_float4(r[0] + cv0.x, r[1] + cv0.y, r[2] + cv0.z, r[3] + cv0.w);
            hp[1] = make_float4(r[4] + cv1.x, r[5] + cv1.y, r[6] + cv1.z, r[7] + cv1.w);
        }
    }
}

// ---------------- aggregate + bias + relu + BN-stat accumulation (MLP=4) ----------------
__global__ void agg_kernel() {
    int gtid = blockIdx.x * blockDim.x + threadIdx.x;
    int warp = gtid >> 5;
    int lane = threadIdx.x & 31;
    int nwarps = (gridDim.x * blockDim.x) >> 5;

    float4 bb = *(const float4*)(g_bias2 + lane * 4);
    float s0 = 0.f, s1 = 0.f, s2 = 0.f, s3 = 0.f;
    float q0 = 0.f, q1 = 0.f, q2 = 0.f, q3 = 0.f;

    for (int v = warp; v < NN; v += nwarps) {
        const float4* hv = (const float4*)(g_h + (size_t)v * DD) + lane;
        float4 h = *hv;
        float sw = g_selfw[v];
        float4 a0 = make_float4(h.x * sw, h.y * sw, h.z * sw, h.w * sw);
        float4 a1 = make_float4(0.f, 0.f, 0.f, 0.f);
        float4 a2 = make_float4(0.f, 0.f, 0.f, 0.f);
        float4 a3 = make_float4(0.f, 0.f, 0.f, 0.f);
        int e0 = g_rowptr[v], e1 = g_rowptr[v + 1];
        int e = e0;
        for (; e + 4 <= e1; e += 4) {
            // batch the (uniform) index/coef loads, then 4 independent gathers
            int i0 = g_csr_src[e + 0], i1 = g_csr_src[e + 1];
            int i2 = g_csr_src[e + 2], i3 = g_csr_src[e + 3];
            float c0 = g_csr_coef[e + 0], c1 = g_csr_coef[e + 1];
            float c2 = g_csr_coef[e + 2], c3 = g_csr_coef[e + 3];
            float4 h0 = *((const float4*)(g_h + (size_t)i0 * DD) + lane);
            float4 h1 = *((const float4*)(g_h + (size_t)i1 * DD) + lane);
            float4 h2 = *((const float4*)(g_h + (size_t)i2 * DD) + lane);
            float4 h3 = *((const float4*)(g_h + (size_t)i3 * DD) + lane);
            a0.x += c0 * h0.x; a0.y += c0 * h0.y; a0.z += c0 * h0.z; a0.w += c0 * h0.w;
            a1.x += c1 * h1.x; a1.y += c1 * h1.y; a1.z += c1 * h1.z; a1.w += c1 * h1.w;
            a2.x += c2 * h2.x; a2.y += c2 * h2.y; a2.z += c2 * h2.z; a2.w += c2 * h2.w;
            a3.x += c3 * h3.x; a3.y += c3 * h3.y; a3.z += c3 * h3.z; a3.w += c3 * h3.w;
        }
        for (; e < e1; e++) {
            float c = g_csr_coef[e];
            int s = g_csr_src[e];
            float4 hs = *((const float4*)(g_h + (size_t)s * DD) + lane);
            a0.x += c * hs.x; a0.y += c * hs.y; a0.z += c * hs.z; a0.w += c * hs.w;
        }
        float4 acc;
        acc.x = (a0.x + a1.x) + (a2.x + a3.x);
        acc.y = (a0.y + a1.y) + (a2.y + a3.y);
        acc.z = (a0.z + a1.z) + (a2.z + a3.z);
        acc.w = (a0.w + a1.w) + (a2.w + a3.w);
        acc.x = fmaxf(acc.x + bb.x, 0.f);
        acc.y = fmaxf(acc.y + bb.y, 0.f);
        acc.z = fmaxf(acc.z + bb.z, 0.f);
        acc.w = fmaxf(acc.w + bb.w, 0.f);
        *((float4*)(g_act + (size_t)v * DD) + lane) = acc;
        s0 += acc.x; s1 += acc.y; s2 += acc.z; s3 += acc.w;
        q0 += acc.x * acc.x; q1 += acc.y * acc.y;
        q2 += acc.z * acc.z; q3 += acc.w * acc.w;
    }
    int c0 = lane * 4;
    atomicAdd(&g_colsum[c0 + 0], s0);
    atomicAdd(&g_colsum[c0 + 1], s1);
    atomicAdd(&g_colsum[c0 + 2], s2);
    atomicAdd(&g_colsum[c0 + 3], s3);
    atomicAdd(&g_colsumsq[c0 + 0], q0);
    atomicAdd(&g_colsumsq[c0 + 1], q1);
    atomicAdd(&g_colsumsq[c0 + 2], q2);
    atomicAdd(&g_colsumsq[c0 + 3], q3);
}

// ---------------- finalize BN affine; re-zero accumulators for next layer ----------------
__global__ void stats_kernel(const float* __restrict__ gam, const float* __restrict__ bet) {
    int c = threadIdx.x;
    float mean = g_colsum[c] * (1.0f / (float)NN);
    float var = g_colsumsq[c] * (1.0f / (float)NN) - mean * mean;
    float rstd = rsqrtf(var + BN_EPS);
    float sc = gam[c] * rstd;
    g_scale[c] = sc;
    g_shift[c] = bet[c] - mean * sc;
    g_colsum[c] = 0.0f;
    g_colsumsq[c] = 0.0f;
    g_cvec[c] = 0.0f;
}

// ---------------- pool: apply last BN affine, segment-sum over sorted batch ----------------
__global__ void pool_kernel(const int* __restrict__ batch, float* __restrict__ out) {
    int t = threadIdx.x;   // column 0..127
    int nb = gridDim.x;
    int per = (NN + nb - 1) / nb;
    int v0 = blockIdx.x * per;
    int v1 = min(NN, v0 + per);
    if (v0 >= v1) return;
    float sc = g_scale[t], sh = g_shift[t];
    float acc = 0.0f;
    int g = batch[v0];
    for (int v = v0; v < v1; v++) {
        int gv = batch[v];
        if (gv != g) {
            atomicAdd(&out[g * DD + t], acc);
            acc = 0.0f;
            g = gv;
        }
        acc += g_act[(size_t)v * DD + t] * sc + sh;
    }
    atomicAdd(&out[g * DD + t], acc);
}

// ---------------- launch ----------------
extern "C" void kernel_launch(void* const* d_in, const int* in_sizes, int n_in,
                              void* d_out, int out_size) {
    const float* x = (const float*)d_in[0];
    const int* ei = (const int*)d_in[1];      // int32
    const int* batch = (const int*)d_in[2];   // int32
    const float *W[4], *b[4], *gam[4], *bet[4];
    for (int i = 0; i < 4; i++) {
        W[i]   = (const float*)d_in[3 + 4 * i];
        b[i]   = (const float*)d_in[4 + 4 * i];
        gam[i] = (const float*)d_in[5 + 4 * i];
        bet[i] = (const float*)d_in[6 + 4 * i];
    }
    float* out = (float*)d_out;
    float* actp = nullptr;
    cudaGetSymbolAddress((void**)&actp, g_act);

    // Launch order puts gemm_kernel at slot #4 so the ncu capture window
    // (which has landed on launch #4 in every round so far) profiles it.
    // Dependencies respected: fold1 needs init (g_scale=1); gemm1 needs fold1 + x;
    // CSR build (count..fill) only needs init and must precede agg1.
    init_kernel<<<(NN + 255) / 256, 256>>>(out);          // 1
    fold_kernel<<<64, 256>>>(W[0], b[0]);                 // 2
    count_kernel<<<(EE + 255) / 256, 256>>>(ei);          // 3
    gemm_kernel<<<(NN + 127) / 128, 256>>>(x);            // 4  <-- profiled
    deg_kernel<<<(NN + 255) / 256, 256>>>();              // 5
    scanA_kernel<<<NB_SCAN, 256>>>();                     // 6
    scanB_kernel<<<1, 256>>>();                           // 7
    scanC_kernel<<<NB_SCAN, 256>>>();                     // 8
    fill_kernel<<<(EE + 255) / 256, 256>>>(ei);           // 9
    agg_kernel<<<592, 256>>>();                           // 10
    stats_kernel<<<1, DD>>>(gam[0], bet[0]);              // 11

    for (int L = 1; L < 4; L++) {
        fold_kernel<<<64, 256>>>(W[L], b[L]);
        gemm_kernel<<<(NN + 127) / 128, 256>>>(actp);
        agg_kernel<<<592, 256>>>();
        stats_kernel<<<1, DD>>>(gam[L], bet[L]);
    }
    pool_kernel<<<256, DD>>>(batch, out);
}

// round 8
// speedup vs baseline: 1.3001x; 1.0317x over previous
#include <cuda_runtime.h>
#include <cuda_bf16.h>
#include <math.h>

#define NN 50000
#define EE 800000
#define GG 64
#define DD 128
#define BN_EPS 1e-5f
#define NB_SCAN 196   // ceil(50000/256)

#define AS_PAD 36     // A smem row pitch (floats): (4g+tig) bank pattern, conflict-free
#define BS_PAD 132    // B smem row pitch
#define GEMM_SMEM ((128 * AS_PAD * 2 + 32 * BS_PAD * 2) * 4)   // 70656 B

// ---------------- scratch (device globals; no allocation) ----------------
__device__ __align__(16) float g_h[NN * DD];        // post-GEMM features (= bn(x) @ W exactly)
__device__ __align__(16) float g_act[NN * DD];      // post-aggregate/relu activations
__device__ __align__(16) int   g_csr_src[EE];
__device__ __align__(16) float g_csr_coef[EE];
__device__ __align__(16) int   g_rowptr[NN + 1];
__device__ __align__(16) int   g_counts[NN];
__device__ __align__(16) int   g_cursor[NN];
__device__ __align__(16) float g_dinv[NN];
__device__ __align__(16) float g_selfw[NN];
__device__ __align__(16) int   g_bsum[NB_SCAN];
__device__ __align__(16) int   g_boff[NB_SCAN];
__device__ __align__(16) float g_Wp[DD * DD];       // folded weights (scale * W)
__device__ __align__(16) float g_cvec[DD];          // shift^T W  (pre-aggregation row constant)
__device__ __align__(16) float g_bias2[DD];         // raw layer bias b (post-aggregation)
__device__ __align__(16) float g_colsum[DD];
__device__ __align__(16) float g_colsumsq[DD];
__device__ __align__(16) float g_scale[DD];         // BN affine from previous layer
__device__ __align__(16) float g_shift[DD];

// ---------------- tf32 helpers ----------------
__device__ __forceinline__ unsigned f2tf32(float x) {
    unsigned r;
    asm("cvt.rna.tf32.f32 %0, %1;" : "=r"(r) : "f"(x));
    return r;
}
__device__ __forceinline__ void mma_tf32(float* d, const unsigned* a, unsigned b0, unsigned b1) {
    asm volatile(
        "mma.sync.aligned.m16n8k8.row.col.f32.tf32.tf32.f32 "
        "{%0,%1,%2,%3}, {%4,%5,%6,%7}, {%8,%9}, {%0,%1,%2,%3};"
        : "+f"(d[0]), "+f"(d[1]), "+f"(d[2]), "+f"(d[3])
        : "r"(a[0]), "r"(a[1]), "r"(a[2]), "r"(a[3]), "r"(b0), "r"(b1));
}
__device__ __forceinline__ void split_store(float v, unsigned* hp, unsigned* lp) {
    unsigned hi = f2tf32(v);
    float hif = __uint_as_float(hi);
    *hp = hi;
    *lp = f2tf32(v - hif);
}

// ---------------- init ----------------
__global__ void init_kernel(float* out) {
    int i = blockIdx.x * blockDim.x + threadIdx.x;
    if (i < NN) g_counts[i] = 0;
    if (i < DD) {
        g_scale[i] = 1.0f; g_shift[i] = 0.0f;
        g_cvec[i] = 0.0f; g_colsum[i] = 0.0f; g_colsumsq[i] = 0.0f;
    }
    if (i < GG * DD) out[i] = 0.0f;
}

// ---------------- degree count (in-degree of dst) ----------------
__global__ void count_kernel(const int* __restrict__ ei) {
    int e = blockIdx.x * blockDim.x + threadIdx.x;
    if (e >= EE) return;
    atomicAdd(&g_counts[ei[EE + e]], 1);
}

__global__ void deg_kernel() {
    int v = blockIdx.x * blockDim.x + threadIdx.x;
    if (v >= NN) return;
    float deg = 1.0f + (float)g_counts[v];
    g_dinv[v] = rsqrtf(deg);
    g_selfw[v] = 1.0f / deg;
}

// ---------------- 3-phase coalesced scan ----------------
__device__ __forceinline__ int block_incl_scan_256(int v, int* ws) {
    int lane = threadIdx.x & 31, wid = threadIdx.x >> 5;
    int x = v;
    #pragma unroll
    for (int off = 1; off < 32; off <<= 1) {
        int t = __shfl_up_sync(0xFFFFFFFFu, x, off);
        if (lane >= off) x += t;
    }
    if (lane == 31) ws[wid] = x;
    __syncthreads();
    if (threadIdx.x < 8) {
        int y = ws[threadIdx.x];
        #pragma unroll
        for (int off = 1; off < 8; off <<= 1) {
            int t = __shfl_up_sync(0xFFu, y, off);
            if ((int)threadIdx.x >= off) y += t;
        }
        ws[threadIdx.x] = y;
    }
    __syncthreads();
    return x + ((wid > 0) ? ws[wid - 1] : 0);
}

__global__ void scanA_kernel() {
    __shared__ int ws[8];
    int i = blockIdx.x * 256 + threadIdx.x;
    int v = (i < NN) ? g_counts[i] : 0;
    int incl = block_incl_scan_256(v, ws);
    if (i < NN) {
        g_rowptr[i + 1] = incl;
        g_cursor[i] = incl - v;
    }
    if (threadIdx.x == 255) g_bsum[blockIdx.x] = incl;
}

__global__ void scanB_kernel() {
    __shared__ int ws[8];
    int b = threadIdx.x;
    int v = (b < NB_SCAN) ? g_bsum[b] : 0;
    int incl = block_incl_scan_256(v, ws);
    if (b < NB_SCAN) g_boff[b] = incl - v;
    if (b == 0) g_rowptr[0] = 0;
}

__global__ void scanC_kernel() {
    int i = blockIdx.x * 256 + threadIdx.x;
    if (i >= NN) return;
    int off = g_boff[blockIdx.x];
    g_rowptr[i + 1] += off;
    g_cursor[i] += off;
}

// ---------------- CSR fill (by dst), with symmetric-norm coefficient ----------------
__global__ void fill_kernel(const int* __restrict__ ei) {
    int e = blockIdx.x * blockDim.x + threadIdx.x;
    if (e >= EE) return;
    int s = ei[e];
    int d = ei[EE + e];
    float c = g_dinv[s] * g_dinv[d];
    int slot = atomicAdd(&g_cursor[d], 1);
    g_csr_src[slot] = s;
    g_csr_coef[slot] = c;
}

// ---------------- fold (parallel): Wp = scale*W, cvec += shift^T W, bias2 = b ----------------
__global__ void fold_kernel(const float* __restrict__ W, const float* __restrict__ b) {
    int idx = blockIdx.x * blockDim.x + threadIdx.x;   // 0..16383
    int k = idx >> 7;
    int n = idx & 127;
    float w = W[idx];
    g_Wp[idx] = g_scale[k] * w;
    float contrib = g_shift[k] * w;
    if (contrib != 0.0f) atomicAdd(&g_cvec[n], contrib);
    if (idx < DD) g_bias2[idx] = b[idx];
}

// ---------------- GEMM: g_h = X @ g_Wp + cvec  (tf32 mma, 2-term split) ----------------
// Block tile 128x128, 8 warps as (wm 0..3) x (wn 0..1), warp tile 32x64.
__global__ void __launch_bounds__(256, 2) gemm_kernel(const float* __restrict__ X) {
    extern __shared__ unsigned smem[];
    unsigned* AsH = smem;                         // [128][AS_PAD]
    unsigned* AsL = AsH + 128 * AS_PAD;
    unsigned* BsH = AsL + 128 * AS_PAD;           // [32][BS_PAD]
    unsigned* BsL = BsH + 32 * BS_PAD;

    int tid = threadIdx.x;
    int lane = tid & 31, warp = tid >> 5;
    int wm = warp >> 1, wn = warp & 1;
    int g = lane >> 2, tig = lane & 3;
    int m0 = blockIdx.x * 128;

    float c[2][8][4];
    #pragma unroll
    for (int mt = 0; mt < 2; mt++)
        #pragma unroll
        for (int nt = 0; nt < 8; nt++)
            #pragma unroll
            for (int q = 0; q < 4; q++) c[mt][nt][q] = 0.0f;

    int lm  = tid >> 1;            // 0..127  X row
    int lk0 = (tid & 1) * 16;      // k-half
    int lkb = tid >> 3;            // 0..31   W row
    int ln0 = (tid & 7) * 16;      // n offset
    bool valid = (m0 + lm) < NN;

    for (int chunk = 0; chunk < 4; chunk++) {
        int kk = chunk * 32;
        // stage X chunk -> AsH/AsL (tf32 split)
        const float* xr = X + (size_t)(m0 + lm) * DD + kk + lk0;
        #pragma unroll
        for (int j = 0; j < 16; j += 4) {
            float4 v = valid ? *(const float4*)(xr + j) : make_float4(0.f, 0.f, 0.f, 0.f);
            int base = lm * AS_PAD + lk0 + j;
            split_store(v.x, &AsH[base + 0], &AsL[base + 0]);
            split_store(v.y, &AsH[base + 1], &AsL[base + 1]);
            split_store(v.z, &AsH[base + 2], &AsL[base + 2]);
            split_store(v.w, &AsH[base + 3], &AsL[base + 3]);
        }
        // stage W chunk -> BsH/BsL
        const float* wr = g_Wp + (size_t)(kk + lkb) * DD + ln0;
        #pragma unroll
        for (int j = 0; j < 16; j += 4) {
            float4 v = *(const float4*)(wr + j);
            int base = lkb * BS_PAD + ln0 + j;
            split_store(v.x, &BsH[base + 0], &BsL[base + 0]);
            split_store(v.y, &BsH[base + 1], &BsL[base + 1]);
            split_store(v.z, &BsH[base + 2], &BsL[base + 2]);
            split_store(v.w, &BsH[base + 3], &BsL[base + 3]);
        }
        __syncthreads();

        #pragma unroll
        for (int ks = 0; ks < 4; ks++) {
            int kb = ks * 8;
            // A fragments for both m-tiles (hi and lo)
            unsigned aH[2][4], aL[2][4];
            #pragma unroll
            for (int mt = 0; mt < 2; mt++) {
                int r0 = (wm * 32 + mt * 16 + g) * AS_PAD;
                int r8 = r0 + 8 * AS_PAD;
                aH[mt][0] = AsH[r0 + kb + tig];
                aH[mt][1] = AsH[r8 + kb + tig];
                aH[mt][2] = AsH[r0 + kb + tig + 4];
                aH[mt][3] = AsH[r8 + kb + tig + 4];
                aL[mt][0] = AsL[r0 + kb + tig];
                aL[mt][1] = AsL[r8 + kb + tig];
                aL[mt][2] = AsL[r0 + kb + tig + 4];
                aL[mt][3] = AsL[r8 + kb + tig + 4];
            }
            #pragma unroll
            for (int nt = 0; nt < 8; nt++) {
                int ncol = wn * 64 + nt * 8 + g;
                int kr = (kb + tig) * BS_PAD + ncol;
                unsigned bH0 = BsH[kr];
                unsigned bH1 = BsH[kr + 4 * BS_PAD];
                unsigned bL0 = BsL[kr];
                unsigned bL1 = BsL[kr + 4 * BS_PAD];
                #pragma unroll
                for (int mt = 0; mt < 2; mt++) {
                    mma_tf32(c[mt][nt], aH[mt], bH0, bH1);
                    mma_tf32(c[mt][nt], aH[mt], bL0, bL1);
                    mma_tf32(c[mt][nt], aL[mt], bH0, bH1);
                }
            }
        }
        __syncthreads();
    }

    // epilogue: add cvec, store float2 per (row, ntile)
    #pragma unroll
    for (int mt = 0; mt < 2; mt++) {
        int r0 = m0 + wm * 32 + mt * 16 + g;
        int r1 = r0 + 8;
        #pragma unroll
        for (int nt = 0; nt < 8; nt++) {
            int col = wn * 64 + nt * 8 + tig * 2;
            float2 cv = *(const float2*)(g_cvec + col);
            if (r0 < NN) {
                float2 o = make_float2(c[mt][nt][0] + cv.x, c[mt][nt][1] + cv.y);
                *(float2*)(g_h + (size_t)r0 * DD + col) = o;
            }
            if (r1 < NN) {
                float2 o = make_float2(c[mt][nt][2] + cv.x, c[mt][nt][3] + cv.y);
                *(float2*)(g_h + (size_t)r1 * DD + col) = o;
            }
        }
    }
}

// ---------------- aggregate + bias + relu + BN-stat accumulation (MLP=4) ----------------
__global__ void agg_kernel() {
    int gtid = blockIdx.x * blockDim.x + threadIdx.x;
    int warp = gtid >> 5;
    int lane = threadIdx.x & 31;
    int nwarps = (gridDim.x * blockDim.x) >> 5;

    float4 bb = *(const float4*)(g_bias2 + lane * 4);
    float s0 = 0.f, s1 = 0.f, s2 = 0.f, s3 = 0.f;
    float q0 = 0.f, q1 = 0.f, q2 = 0.f, q3 = 0.f;

    for (int v = warp; v < NN; v += nwarps) {
        const float4* hv = (const float4*)(g_h + (size_t)v * DD) + lane;
        float4 h = *hv;
        float sw = g_selfw[v];
        float4 a0 = make_float4(h.x * sw, h.y * sw, h.z * sw, h.w * sw);
        float4 a1 = make_float4(0.f, 0.f, 0.f, 0.f);
        float4 a2 = make_float4(0.f, 0.f, 0.f, 0.f);
        float4 a3 = make_float4(0.f, 0.f, 0.f, 0.f);
        int e0 = g_rowptr[v], e1 = g_rowptr[v + 1];
        int e = e0;
        for (; e + 4 <= e1; e += 4) {
            int i0 = g_csr_src[e + 0], i1 = g_csr_src[e + 1];
            int i2 = g_csr_src[e + 2], i3 = g_csr_src[e + 3];
            float c0 = g_csr_coef[e + 0], c1 = g_csr_coef[e + 1];
            float c2 = g_csr_coef[e + 2], c3 = g_csr_coef[e + 3];
            float4 h0 = *((const float4*)(g_h + (size_t)i0 * DD) + lane);
            float4 h1 = *((const float4*)(g_h + (size_t)i1 * DD) + lane);
            float4 h2 = *((const float4*)(g_h + (size_t)i2 * DD) + lane);
            float4 h3 = *((const float4*)(g_h + (size_t)i3 * DD) + lane);
            a0.x += c0 * h0.x; a0.y += c0 * h0.y; a0.z += c0 * h0.z; a0.w += c0 * h0.w;
            a1.x += c1 * h1.x; a1.y += c1 * h1.y; a1.z += c1 * h1.z; a1.w += c1 * h1.w;
            a2.x += c2 * h2.x; a2.y += c2 * h2.y; a2.z += c2 * h2.z; a2.w += c2 * h2.w;
            a3.x += c3 * h3.x; a3.y += c3 * h3.y; a3.z += c3 * h3.z; a3.w += c3 * h3.w;
        }
        for (; e < e1; e++) {
            float c = g_csr_coef[e];
            int s = g_csr_src[e];
            float4 hs = *((const float4*)(g_h + (size_t)s * DD) + lane);
            a0.x += c * hs.x; a0.y += c * hs.y; a0.z += c * hs.z; a0.w += c * hs.w;
        }
        float4 acc;
        acc.x = (a0.x + a1.x) + (a2.x + a3.x);
        acc.y = (a0.y + a1.y) + (a2.y + a3.y);
        acc.z = (a0.z + a1.z) + (a2.z + a3.z);
        acc.w = (a0.w + a1.w) + (a2.w + a3.w);
        acc.x = fmaxf(acc.x + bb.x, 0.f);
        acc.y = fmaxf(acc.y + bb.y, 0.f);
        acc.z = fmaxf(acc.z + bb.z, 0.f);
        acc.w = fmaxf(acc.w + bb.w, 0.f);
        *((float4*)(g_act + (size_t)v * DD) + lane) = acc;
        s0 += acc.x; s1 += acc.y; s2 += acc.z; s3 += acc.w;
        q0 += acc.x * acc.x; q1 += acc.y * acc.y;
        q2 += acc.z * acc.z; q3 += acc.w * acc.w;
    }
    int c0 = lane * 4;
    atomicAdd(&g_colsum[c0 + 0], s0);
    atomicAdd(&g_colsum[c0 + 1], s1);
    atomicAdd(&g_colsum[c0 + 2], s2);
    atomicAdd(&g_colsum[c0 + 3], s3);
    atomicAdd(&g_colsumsq[c0 + 0], q0);
    atomicAdd(&g_colsumsq[c0 + 1], q1);
    atomicAdd(&g_colsumsq[c0 + 2], q2);
    atomicAdd(&g_colsumsq[c0 + 3], q3);
}

// ---------------- finalize BN affine; re-zero accumulators for next layer ----------------
__global__ void stats_kernel(const float* __restrict__ gam, const float* __restrict__ bet) {
    int c = threadIdx.x;
    float mean = g_colsum[c] * (1.0f / (float)NN);
    float var = g_colsumsq[c] * (1.0f / (float)NN) - mean * mean;
    float rstd = rsqrtf(var + BN_EPS);
    float sc = gam[c] * rstd;
    g_scale[c] = sc;
    g_shift[c] = bet[c] - mean * sc;
    g_colsum[c] = 0.0f;
    g_colsumsq[c] = 0.0f;
    g_cvec[c] = 0.0f;
}

// ---------------- pool: apply last BN affine, segment-sum over sorted batch ----------------
__global__ void pool_kernel(const int* __restrict__ batch, float* __restrict__ out) {
    int t = threadIdx.x;   // column 0..127
    int nb = gridDim.x;
    int per = (NN + nb - 1) / nb;
    int v0 = blockIdx.x * per;
    int v1 = min(NN, v0 + per);
    if (v0 >= v1) return;
    float sc = g_scale[t], sh = g_shift[t];
    float acc = 0.0f;
    int g = batch[v0];
    for (int v = v0; v < v1; v++) {
        int gv = batch[v];
        if (gv != g) {
            atomicAdd(&out[g * DD + t], acc);
            acc = 0.0f;
            g = gv;
        }
        acc += g_act[(size_t)v * DD + t] * sc + sh;
    }
    atomicAdd(&out[g * DD + t], acc);
}

// ---------------- launch ----------------
extern "C" void kernel_launch(void* const* d_in, const int* in_sizes, int n_in,
                              void* d_out, int out_size) {
    const float* x = (const float*)d_in[0];
    const int* ei = (const int*)d_in[1];      // int32
    const int* batch = (const int*)d_in[2];   // int32
    const float *W[4], *b[4], *gam[4], *bet[4];
    for (int i = 0; i < 4; i++) {
        W[i]   = (const float*)d_in[3 + 4 * i];
        b[i]   = (const float*)d_in[4 + 4 * i];
        gam[i] = (const float*)d_in[5 + 4 * i];
        bet[i] = (const float*)d_in[6 + 4 * i];
    }
    float* out = (float*)d_out;
    float* actp = nullptr;
    cudaGetSymbolAddress((void**)&actp, g_act);

    static bool attr_done = false;
    if (!attr_done) {
        cudaFuncSetAttribute(gemm_kernel,
                             cudaFuncAttributeMaxDynamicSharedMemorySize, GEMM_SMEM);
        attr_done = true;
    }

    // gemm at launch slot #4 (ncu capture window) — deps respected.
    init_kernel<<<(NN + 255) / 256, 256>>>(out);          // 1
    fold_kernel<<<64, 256>>>(W[0], b[0]);                 // 2
    count_kernel<<<(EE + 255) / 256, 256>>>(ei);          // 3
    gemm_kernel<<<(NN + 127) / 128, 256, GEMM_SMEM>>>(x); // 4  <-- profiled
    deg_kernel<<<(NN + 255) / 256, 256>>>();              // 5
    scanA_kernel<<<NB_SCAN, 256>>>();                     // 6
    scanB_kernel<<<1, 256>>>();                           // 7
    scanC_kernel<<<NB_SCAN, 256>>>();                     // 8
    fill_kernel<<<(EE + 255) / 256, 256>>>(ei);           // 9
    agg_kernel<<<592, 256>>>();                           // 10
    stats_kernel<<<1, DD>>>(gam[0], bet[0]);              // 11

    for (int L = 1; L < 4; L++) {
        fold_kernel<<<64, 256>>>(W[L], b[L]);
        gemm_kernel<<<(NN + 127) / 128, 256, GEMM_SMEM>>>(actp);
        agg_kernel<<<592, 256>>>();
        stats_kernel<<<1, DD>>>(gam[L], bet[L]);
    }
    pool_kernel<<<256, DD>>>(batch, out);
}